// round 5
// baseline (speedup 1.0000x reference)
#include <cuda_runtime.h>
#include <cstdint>

constexpr int CN = 384;
constexpr int NHEAD = 4;
constexpr int HDIM = 96;
constexpr int HH = 64;
constexpr int WW = 128;
constexpr int HW = HH * WW;   // 8192
constexpr int BB = 8;

// Scratch (device globals: allocation-free, harness-legal)
__device__ float g_q[BB * CN * HW];
__device__ float g_kv[BB * 2 * CN * HW];
__device__ float g_ao[BB * CN * HW];
__device__ float g_o2[BB * CN * HW];
__device__ float g_psum[BB * CN];
__device__ float g_psq[BB * CN];
__device__ float g_scale[CN];
__device__ float g_shift[CN];

__device__ __forceinline__ float to_tf32(float x) {
    uint32_t u;
    asm("cvt.rna.tf32.f32 %0, %1;" : "=r"(u) : "f"(x));
    return __uint_as_float(u);
}
__device__ __forceinline__ void mma_tf32(float4& d, const uint32_t a[4], const uint32_t b[2]) {
    asm volatile(
        "mma.sync.aligned.m16n8k8.row.col.f32.tf32.tf32.f32 "
        "{%0,%1,%2,%3}, {%4,%5,%6,%7}, {%8,%9}, {%0,%1,%2,%3};\n"
        : "+f"(d.x), "+f"(d.y), "+f"(d.z), "+f"(d.w)
        : "r"(a[0]), "r"(a[1]), "r"(a[2]), "r"(a[3]), "r"(b[0]), "r"(b[1]));
}
__device__ __forceinline__ uint32_t smem_u32(const void* p) {
    uint32_t a;
    asm("{ .reg .u64 t; cvta.to.shared.u64 t, %1; cvt.u32.u64 %0, t; }" : "=r"(a) : "l"(p));
    return a;
}
__device__ __forceinline__ void cp16(uint32_t d, const void* g) {
    asm volatile("cp.async.cg.shared.global [%0], [%1], 16;" :: "r"(d), "l"(g));
}

// ===========================================================================
// Projection GEMM: legacy tf32 mma + cp.async pipeline.
// Block tile 128(M) x 128(N), K-tile 16, 4 buffers / 3 outstanding.
// 128 threads = 4 warps, each 64x64 (4 m-tiles x 8 n-tiles of m16n8).
//   Y[(bz*M + m)*HW + n] = epi( sum_c A[m][c] * X[(bz*Cin + c)*HW + n] + bias[m] )
// A rows split (A0|A1) at Msplit; X channels split (X0|X1) at Ksplit.
// MODE 0: plain store. MODE 1: gate epilogue  Y = fs + sigmoid(v) * o2.
// fp32 values fed to HMMA directly (HW tf32 truncation).
// ===========================================================================
constexpr int APADC = 20;                 // A row stride (floats), conflict-free
constexpr int BPADC = 136;                // B row stride (floats), conflict-free
constexpr int ASTG = 128 * APADC;         // 2560 floats
constexpr int BSTG = 16 * BPADC;          // 2176 floats
constexpr int STG = ASTG + BSTG;          // 4736 floats per stage
constexpr int GSMEM2 = 4 * STG * 4;       // 75,776 B

template <int MODE>
__global__ __launch_bounds__(128, 2)
void gemm_cp(const float* __restrict__ A0, const float* __restrict__ A1,
             int Msplit, int lda,
             const float* __restrict__ bias0, const float* __restrict__ bias1,
             const float* __restrict__ X0, const float* __restrict__ X1,
             int Ksplit, int M, int K,
             float* __restrict__ Y,
             const float* __restrict__ fs, const float* __restrict__ o2)
{
    extern __shared__ float smf[];
    const uint32_t sb = smem_u32(smf);
    const int tid = threadIdx.x;
    const int lane = tid & 31;
    const int warp = tid >> 5;
    const int group = lane >> 2;
    const int tig = lane & 3;
    const int wm = warp & 1;
    const int wn = warp >> 1;
    const int row0 = blockIdx.x * 128;
    const int col0 = blockIdx.y * 128;
    const int bz = blockIdx.z;
    const int C1 = K - Ksplit;
    const int KT = K >> 4;

    // loader maps (128 threads)
    const int mg = row0 + tid;                       // A row
    const float* arow = (mg < Msplit) ? (A0 + (size_t)mg * lda)
                                      : (A1 + (size_t)(mg - Msplit) * lda);
    const int br = tid >> 3;                         // B k-row 0..15
    const int bc = (tid & 7) * 16;                   // B col chunk base (floats)

    auto xrow = [&](int cg) -> const float* {
        return (cg < Ksplit) ? (X0 + ((size_t)bz * Ksplit + cg) * HW)
                             : (X1 + ((size_t)bz * C1 + (cg - Ksplit)) * HW);
    };

    auto load_tile = [&](int kt) {
        const uint32_t base = sb + (kt & 3) * (STG * 4);
        const float* as = arow + kt * 16;
        const uint32_t adst = base + (tid * APADC) * 4;
#pragma unroll
        for (int j = 0; j < 4; j++) cp16(adst + j * 16, as + j * 4);
        const float* xr = xrow(kt * 16 + br) + col0 + bc;
        const uint32_t bdst = base + (ASTG + br * BPADC + bc) * 4;
#pragma unroll
        for (int j = 0; j < 4; j++) cp16(bdst + j * 16, xr + j * 4);
        asm volatile("cp.async.commit_group;" ::: "memory");
    };

    float4 acc[4][8];
#pragma unroll
    for (int i = 0; i < 4; i++)
#pragma unroll
        for (int j = 0; j < 8; j++) acc[i][j] = make_float4(0.f, 0.f, 0.f, 0.f);

    // prologue: 3 tiles in flight
    load_tile(0);
    load_tile(1);
    load_tile(2);

    for (int kt = 0; kt < KT; kt++) {
        // wait until tile kt is resident
        if (kt + 2 <= KT - 1)      asm volatile("cp.async.wait_group 2;" ::: "memory");
        else if (kt + 1 <= KT - 1) asm volatile("cp.async.wait_group 1;" ::: "memory");
        else                       asm volatile("cp.async.wait_group 0;" ::: "memory");
        __syncthreads();

        // refill the buffer freed by tile kt-1
        if (kt + 3 < KT) load_tile(kt + 3);

        const float* Ab = smf + (kt & 3) * STG;
        const float* Bb = Ab + ASTG;
#pragma unroll
        for (int kk = 0; kk < 16; kk += 8) {
            uint32_t a[4][4], b[8][2];
#pragma unroll
            for (int mt = 0; mt < 4; mt++) {
                const int r = wm * 64 + mt * 16 + group;
                a[mt][0] = __float_as_uint(Ab[r * APADC + kk + tig]);
                a[mt][1] = __float_as_uint(Ab[(r + 8) * APADC + kk + tig]);
                a[mt][2] = __float_as_uint(Ab[r * APADC + kk + tig + 4]);
                a[mt][3] = __float_as_uint(Ab[(r + 8) * APADC + kk + tig + 4]);
            }
#pragma unroll
            for (int nt = 0; nt < 8; nt++) {
                const int c = wn * 64 + nt * 8 + group;
                b[nt][0] = __float_as_uint(Bb[(kk + tig) * BPADC + c]);
                b[nt][1] = __float_as_uint(Bb[(kk + tig + 4) * BPADC + c]);
            }
#pragma unroll
            for (int mt = 0; mt < 4; mt++)
#pragma unroll
                for (int nt = 0; nt < 8; nt++)
                    mma_tf32(acc[mt][nt], a[mt], b[nt]);
        }
    }

    // ---- epilogue ----
#pragma unroll
    for (int mt = 0; mt < 4; mt++) {
        const int r0 = row0 + wm * 64 + mt * 16 + group;
        const int r1 = r0 + 8;
        const float bia0 = (r0 < Msplit) ? bias0[r0] : bias1[r0 - Msplit];
        const float bia1 = (r1 < Msplit) ? bias0[r1] : bias1[r1 - Msplit];
#pragma unroll
        for (int nt = 0; nt < 8; nt++) {
            const int n = col0 + wn * 64 + nt * 8 + tig * 2;
            const size_t i0 = ((size_t)bz * M + r0) * HW + n;
            const size_t i1 = ((size_t)bz * M + r1) * HW + n;
            const float4 c = acc[mt][nt];
            if (MODE == 0) {
                *(float2*)(Y + i0) = make_float2(c.x + bia0, c.y + bia0);
                *(float2*)(Y + i1) = make_float2(c.z + bia1, c.w + bia1);
            } else {
                const float2 f0 = *(const float2*)(fs + i0);
                const float2 f1 = *(const float2*)(fs + i1);
                const float2 q0 = *(const float2*)(o2 + i0);
                const float2 q1 = *(const float2*)(o2 + i1);
                float v; float2 r;
                v = c.x + bia0; r.x = f0.x + q0.x / (1.f + __expf(-v));
                v = c.y + bia0; r.y = f0.y + q0.y / (1.f + __expf(-v));
                *(float2*)(Y + i0) = r;
                v = c.z + bia1; r.x = f1.x + q1.x / (1.f + __expf(-v));
                v = c.w + bia1; r.y = f1.y + q1.y / (1.f + __expf(-v));
                *(float2*)(Y + i1) = r;
            }
        }
    }
}

// ===========================================================================
// Epipolar attention (tf32 legacy mma, round-3 proven). One block per (h,n,b).
// ===========================================================================
constexpr int SP = 136;
constexpr int ATT_SMEM = (HDIM + HDIM + WW) * SP * 4;  // 174,080 B

__global__ __launch_bounds__(256, 1)
void attn_k(const float* __restrict__ q, const float* __restrict__ kv,
            float* __restrict__ ao)
{
    extern __shared__ float sm[];
    float* Qs = sm;
    float* Ks = sm + HDIM * SP;
    float* Ss = sm + 2 * HDIM * SP;
    const int h = blockIdx.x, n = blockIdx.y, b = blockIdx.z;
    const int tid = threadIdx.x;
    const int lane = tid & 31;
    const int warp = tid >> 5;
    const int group = lane >> 2;
    const int tig = lane & 3;

    const size_t qbase = (((size_t)b * CN + n * HDIM) * HH + h) * WW;
    const size_t kbase = (((size_t)b * 2 * CN + n * HDIM) * HH + h) * WW;
    const size_t vbase = kbase + (size_t)CN * HW;

    {
        const int l4 = lane * 4;
#pragma unroll
        for (int it = 0; it < 12; it++) {
            const int cc = warp + it * 8;
            float4 a = *(const float4*)(q + qbase + (size_t)cc * HW + l4);
            float4 c = *(const float4*)(kv + kbase + (size_t)cc * HW + l4);
            *(float4*)&Qs[cc * SP + l4] =
                make_float4(to_tf32(a.x), to_tf32(a.y), to_tf32(a.z), to_tf32(a.w));
            *(float4*)&Ks[cc * SP + l4] =
                make_float4(to_tf32(c.x), to_tf32(c.y), to_tf32(c.z), to_tf32(c.w));
        }
    }
    __syncthreads();

    {   // GEMM1: S[wp][w] = scale * sum_cc K[cc][wp] * Q[cc][w]
        const int wm = warp & 1, wn = warp >> 1;
        float4 acc[4][4];
#pragma unroll
        for (int i = 0; i < 4; i++)
#pragma unroll
            for (int j = 0; j < 4; j++) acc[i][j] = make_float4(0.f, 0.f, 0.f, 0.f);
#pragma unroll
        for (int kk = 0; kk < HDIM; kk += 8) {
            uint32_t a[4][4], bfr[4][2];
#pragma unroll
            for (int mt = 0; mt < 4; mt++) {
                const int wp = wm * 64 + mt * 16 + group;
                a[mt][0] = __float_as_uint(Ks[(kk + tig) * SP + wp]);
                a[mt][1] = __float_as_uint(Ks[(kk + tig) * SP + wp + 8]);
                a[mt][2] = __float_as_uint(Ks[(kk + tig + 4) * SP + wp]);
                a[mt][3] = __float_as_uint(Ks[(kk + tig + 4) * SP + wp + 8]);
            }
#pragma unroll
            for (int nt = 0; nt < 4; nt++) {
                const int w = wn * 32 + nt * 8 + group;
                bfr[nt][0] = __float_as_uint(Qs[(kk + tig) * SP + w]);
                bfr[nt][1] = __float_as_uint(Qs[(kk + tig + 4) * SP + w]);
            }
#pragma unroll
            for (int mt = 0; mt < 4; mt++)
#pragma unroll
                for (int nt = 0; nt < 4; nt++)
                    mma_tf32(acc[mt][nt], a[mt], bfr[nt]);
        }
        const float scale = 0.10206207261596575f;
#pragma unroll
        for (int mt = 0; mt < 4; mt++) {
            const int wp = wm * 64 + mt * 16 + group;
#pragma unroll
            for (int nt = 0; nt < 4; nt++) {
                const int w = wn * 32 + nt * 8 + tig * 2;
                const float4 c = acc[mt][nt];
                *(float2*)&Ss[wp * SP + w] = make_float2(c.x * scale, c.y * scale);
                *(float2*)&Ss[(wp + 8) * SP + w] = make_float2(c.z * scale, c.w * scale);
            }
        }
    }
    __syncthreads();

    if (tid < WW) {
        const int w = tid;
        float mx = -1e30f;
#pragma unroll 8
        for (int wp = 0; wp < WW; wp++) mx = fmaxf(mx, Ss[wp * SP + w]);
        float s = 0.f;
#pragma unroll 8
        for (int wp = 0; wp < WW; wp++) {
            const float e = __expf(Ss[wp * SP + w] - mx);
            Ss[wp * SP + w] = e;
            s += e;
        }
        const float inv = 1.f / s;
#pragma unroll 8
        for (int wp = 0; wp < WW; wp++) Ss[wp * SP + w] = to_tf32(Ss[wp * SP + w] * inv);
    } else {
        const int t = tid - 128;
        const int l4 = (t & 31) * 4;
        const int r0 = t >> 5;
#pragma unroll
        for (int it = 0; it < 24; it++) {
            const int cc = r0 + it * 4;
            float4 c = *(const float4*)(kv + vbase + (size_t)cc * HW + l4);
            *(float4*)&Ks[cc * SP + l4] =
                make_float4(to_tf32(c.x), to_tf32(c.y), to_tf32(c.z), to_tf32(c.w));
        }
    }
    __syncthreads();

    if (warp < 6) {
        const int m0 = warp * 16;
        float4 acc[16];
#pragma unroll
        for (int j = 0; j < 16; j++) acc[j] = make_float4(0.f, 0.f, 0.f, 0.f);
#pragma unroll 4
        for (int kk = 0; kk < WW; kk += 8) {
            uint32_t a[4], bfr[16][2];
            a[0] = __float_as_uint(Ks[(m0 + group) * SP + kk + tig]);
            a[1] = __float_as_uint(Ks[(m0 + group + 8) * SP + kk + tig]);
            a[2] = __float_as_uint(Ks[(m0 + group) * SP + kk + tig + 4]);
            a[3] = __float_as_uint(Ks[(m0 + group + 8) * SP + kk + tig + 4]);
#pragma unroll
            for (int nt = 0; nt < 16; nt++) {
                const int w = nt * 8 + group;
                bfr[nt][0] = __float_as_uint(Ss[(kk + tig) * SP + w]);
                bfr[nt][1] = __float_as_uint(Ss[(kk + tig + 4) * SP + w]);
            }
#pragma unroll
            for (int nt = 0; nt < 16; nt++)
                mma_tf32(acc[nt], a, bfr[nt]);
        }
#pragma unroll
        for (int nt = 0; nt < 16; nt++) {
            const int w = nt * 8 + tig * 2;
            const float4 c = acc[nt];
            *(float2*)(ao + qbase + (size_t)(m0 + group) * HW + w) = make_float2(c.x, c.y);
            *(float2*)(ao + qbase + (size_t)(m0 + group + 8) * HW + w) = make_float2(c.z, c.w);
        }
    }
}

// ===========================================================================
// BatchNorm (training-mode batch stats), 3 stages, no atomics
// ===========================================================================
__global__ __launch_bounds__(256)
void bnstats_k(const float* __restrict__ y)
{
    const int bc = blockIdx.x;
    const float4* p = (const float4*)(y + (size_t)bc * HW);
    const int tid = threadIdx.x;
    float s = 0.f, sq = 0.f;
#pragma unroll
    for (int it = 0; it < 8; it++) {
        const float4 v = p[tid + it * 256];
        s += v.x + v.y + v.z + v.w;
        sq += v.x * v.x + v.y * v.y + v.z * v.z + v.w * v.w;
    }
#pragma unroll
    for (int o = 16; o > 0; o >>= 1) {
        s += __shfl_down_sync(0xffffffffu, s, o);
        sq += __shfl_down_sync(0xffffffffu, sq, o);
    }
    __shared__ float ss[8], sqq[8];
    if ((tid & 31) == 0) { ss[tid >> 5] = s; sqq[tid >> 5] = sq; }
    __syncthreads();
    if (tid == 0) {
        float ts = 0.f, tq = 0.f;
#pragma unroll
        for (int i = 0; i < 8; i++) { ts += ss[i]; tq += sqq[i]; }
        g_psum[bc] = ts;
        g_psq[bc] = tq;
    }
}

__global__ void bnfin_k(const float* __restrict__ gamma,
                        const float* __restrict__ beta)
{
    const int c = threadIdx.x;
    float s = 0.f, sq = 0.f;
#pragma unroll
    for (int b = 0; b < BB; b++) { s += g_psum[b * CN + c]; sq += g_psq[b * CN + c]; }
    const float invN = 1.f / (float)(BB * HW);
    const float mean = s * invN;
    const float var = sq * invN - mean * mean;
    const float inv = rsqrtf(var + 1e-5f);
    const float sc = gamma[c] * inv;
    g_scale[c] = sc;
    g_shift[c] = beta[c] - mean * sc;
}

__global__ void bnapply_k(float* __restrict__ y)
{
    const size_t i = ((size_t)blockIdx.x * 256 + threadIdx.x) * 4;
    const int c = (int)((i >> 13) % CN);
    float4 v = *(float4*)(y + i);
    const float sc = g_scale[c], sh = g_shift[c];
    v.x = v.x * sc + sh;
    v.y = v.y * sc + sh;
    v.z = v.z * sc + sh;
    v.w = v.w * sc + sh;
    *(float4*)(y + i) = v;
}

// ===========================================================================
extern "C" void kernel_launch(void* const* d_in, const int* in_sizes, int n_in,
                              void* d_out, int out_size)
{
    (void)in_sizes; (void)n_in; (void)out_size;
    const float* fs    = (const float*)d_in[0];
    const float* fo    = (const float*)d_in[1];
    const float* wq    = (const float*)d_in[2];
    const float* bq    = (const float*)d_in[3];
    const float* wk    = (const float*)d_in[4];
    const float* bk    = (const float*)d_in[5];
    const float* wv    = (const float*)d_in[6];
    const float* bv    = (const float*)d_in[7];
    const float* wo    = (const float*)d_in[8];
    const float* bo    = (const float*)d_in[9];
    const float* wg    = (const float*)d_in[10];
    const float* bg    = (const float*)d_in[11];
    const float* gamma = (const float*)d_in[12];
    const float* beta  = (const float*)d_in[13];
    float* out = (float*)d_out;

    float *q, *kvb, *ao, *o2;
    cudaGetSymbolAddress((void**)&q,   g_q);
    cudaGetSymbolAddress((void**)&kvb, g_kv);
    cudaGetSymbolAddress((void**)&ao,  g_ao);
    cudaGetSymbolAddress((void**)&o2,  g_o2);

    cudaFuncSetAttribute(gemm_cp<0>, cudaFuncAttributeMaxDynamicSharedMemorySize, GSMEM2);
    cudaFuncSetAttribute(gemm_cp<1>, cudaFuncAttributeMaxDynamicSharedMemorySize, GSMEM2);
    cudaFuncSetAttribute(attn_k, cudaFuncAttributeMaxDynamicSharedMemorySize, ATT_SMEM);

    // Q = wq @ feat_self + bq
    gemm_cp<0><<<dim3(3, 64, 8), 128, GSMEM2>>>(wq, wq, CN, CN, bq, bq,
                                                fs, fs, CN, CN, CN, q, nullptr, nullptr);
    // [K;V] = [wk;wv] @ feat_other + [bk;bv]
    gemm_cp<0><<<dim3(6, 64, 8), 128, GSMEM2>>>(wk, wv, CN, CN, bk, bv,
                                                fo, fo, CN, 2 * CN, CN, kvb, nullptr, nullptr);
    // attention
    attn_k<<<dim3(HH, NHEAD, BB), 256, ATT_SMEM>>>(q, kvb, ao);
    // out2 = wo @ attn_out + bo
    gemm_cp<0><<<dim3(3, 64, 8), 128, GSMEM2>>>(wo, wo, CN, CN, bo, bo,
                                                ao, ao, CN, CN, CN, o2, nullptr, nullptr);
    // fused = fs + sigmoid(wg @ [fs; out2] + bg) * out2  -> d_out
    gemm_cp<1><<<dim3(3, 64, 8), 128, GSMEM2>>>(wg, wg, CN, 2 * CN, bg, bg,
                                                fs, o2, CN, CN, 2 * CN, out, fs, o2);
    // BatchNorm
    bnstats_k<<<BB * CN, 256>>>(out);
    bnfin_k<<<1, CN>>>(gamma, beta);
    bnapply_k<<<BB * CN * HW / 1024, 256>>>(out);
}